// round 14
// baseline (speedup 1.0000x reference)
#include <cuda_runtime.h>
#include <cuda_fp16.h>
#include <cstdint>

// Problem constants
#define BT    8192
#define KCB   8192
#define DDIM  128
#define TLEN  1024
#define CCH   256
#define NQ    2097152
#define NIDX  16384
#define NCANDG 6            // max in-window GROUPS (8 k's each)

// ---------------------------------------------------------------------------
// Scratch (device globals; no allocation allowed)
// ---------------------------------------------------------------------------
__device__ __align__(16) unsigned g_Ahat[16384 * 64];  // f16x2 xh row (256B each)
__device__ __align__(16) unsigned g_Bhat[16384 * 64];  // f16x2 ch row (256B each)
__device__ float  g_c2[2 * KCB];
__device__ float  g_x2[2 * BT];
__device__ float  g_ex2[2 * BT];     // ||x - xh||^2  (exact)
__device__ float  g_xh2[2 * BT];     // ||xh||^2      (exact)
__device__ int    g_c2max_bits[2];   // max_k ||c_k||^2   (float bits)
__device__ int    g_ec2max_bits[2];  // max_k ||c-ch||^2  (float bits)
__device__ int    g_candk[2 * BT * NCANDG];   // group kbases
__device__ int    g_candn[2 * BT];   // group count, or -1 => fallback
__device__ int    g_idx[2 * BT];
__device__ int    g_flagq[2 * BT];
__device__ int    g_nflag;
__device__ double g_sse;

// ---------------------------------------------------------------------------
// PTX helpers (compute_103-legal only: ldmatrix / mma.sync / cp.async)
// ---------------------------------------------------------------------------
__device__ __forceinline__ uint32_t smem_u32(const void* p) {
    uint32_t a;
    asm("{ .reg .u64 t; cvta.to.shared.u64 t, %1; cvt.u32.u64 %0, t; }"
        : "=r"(a) : "l"(p));
    return a;
}
__device__ __forceinline__ void ldsm4(uint32_t& r0, uint32_t& r1,
                                      uint32_t& r2, uint32_t& r3, uint32_t a) {
    asm volatile("ldmatrix.sync.aligned.m8n8.x4.shared.b16 {%0,%1,%2,%3}, [%4];"
                 : "=r"(r0), "=r"(r1), "=r"(r2), "=r"(r3) : "r"(a));
}
__device__ __forceinline__ void mma_f16(float* d, uint32_t a0, uint32_t a1,
                                        uint32_t a2, uint32_t a3,
                                        uint32_t b0, uint32_t b1) {
    asm volatile(
        "mma.sync.aligned.m16n8k16.row.col.f32.f16.f16.f32 "
        "{%0,%1,%2,%3}, {%4,%5,%6,%7}, {%8,%9}, {%0,%1,%2,%3};"
        : "+f"(d[0]), "+f"(d[1]), "+f"(d[2]), "+f"(d[3])
        : "r"(a0), "r"(a1), "r"(a2), "r"(a3), "r"(b0), "r"(b1));
}
__device__ __forceinline__ void cp_async16(uint32_t dst, const void* src) {
    asm volatile("cp.async.cg.shared.global [%0], [%1], 16;"
                 :: "r"(dst), "l"(src) : "memory");
}
#define CP_COMMIT() asm volatile("cp.async.commit_group;" ::: "memory")
#define CP_WAIT0()  asm volatile("cp.async.wait_group 0;" ::: "memory")
#define CP_WAIT1()  asm volatile("cp.async.wait_group 1;" ::: "memory")

__device__ __forceinline__ unsigned pack_h2(__half a, __half b) {
    unsigned short ua = __half_as_ushort(a), ub = __half_as_ushort(b);
    return (unsigned)ua | ((unsigned)ub << 16);
}

// branchless top-6 insert of (s, gi): pure FSETP/SEL, no BSSY/BSYNC.
// Deeper slots updated first using pre-update shallower values.
#define BTOP6(s, gi, V1, V2, V3, V4, V5, V6, G1, G2, G3, G4, G5) do {        \
    bool l1 = (s) < V1, l2 = (s) < V2, l3 = (s) < V3;                        \
    bool l4 = (s) < V4, l5 = (s) < V5, l6 = (s) < V6;                        \
    V6 = l6 ? (l5 ? V5 : (s)) : V6;                                          \
    V5 = l5 ? (l4 ? V4 : (s)) : V5;  G5 = l5 ? (l4 ? G4 : (gi)) : G5;        \
    V4 = l4 ? (l3 ? V3 : (s)) : V4;  G4 = l4 ? (l3 ? G3 : (gi)) : G4;        \
    V3 = l3 ? (l2 ? V2 : (s)) : V3;  G3 = l3 ? (l2 ? G2 : (gi)) : G3;        \
    V2 = l2 ? (l1 ? V1 : (s)) : V2;  G2 = l2 ? (l1 ? G1 : (gi)) : G2;        \
    V1 = l1 ? (s) : V1;              G1 = l1 ? (gi) : G1;                    \
} while (0)

// ---------------------------------------------------------------------------
__global__ void init_kernel() {
    if (blockIdx.x == 0 && threadIdx.x == 0) {
        g_sse = 0.0; g_nflag = 0;
        g_c2max_bits[0] = 0; g_c2max_bits[1] = 0;
        g_ec2max_bits[0] = 0; g_ec2max_bits[1] = 0;
    }
}

// splitcb: one warp per codeword row -> Bhat(f16 ch), c2, max c2, max ||ec||^2
__global__ void splitcb_kernel(const float* __restrict__ cb) {
    int row  = blockIdx.x * 8 + (threadIdx.x >> 5);
    int lane = threadIdx.x & 31;
    const float4 v = *reinterpret_cast<const float4*>(
        cb + (size_t)row * DDIM + lane * 4);
    __half h0 = __float2half_rn(v.x), h1 = __float2half_rn(v.y);
    __half h2 = __float2half_rn(v.z), h3 = __float2half_rn(v.w);
    g_Bhat[(size_t)row * 64 + 2 * lane]     = pack_h2(h0, h1);
    g_Bhat[(size_t)row * 64 + 2 * lane + 1] = pack_h2(h2, h3);
    float e0 = v.x - __half2float(h0), e1 = v.y - __half2float(h1);
    float e2 = v.z - __half2float(h2), e3 = v.w - __half2float(h3);
    float c2  = v.x * v.x + v.y * v.y + v.z * v.z + v.w * v.w;
    float ec2 = e0 * e0 + e1 * e1 + e2 * e2 + e3 * e3;
    #pragma unroll
    for (int o = 16; o; o >>= 1) {
        c2  += __shfl_down_sync(0xFFFFFFFFu, c2, o);
        ec2 += __shfl_down_sync(0xFFFFFFFFu, ec2, o);
    }
    if (lane == 0) {
        g_c2[row] = c2;
        atomicMax(&g_c2max_bits[row >> 13], __float_as_int(c2));
        atomicMax(&g_ec2max_bits[row >> 13], __float_as_int(ec2));
    }
}

// split_x: f16 quantize queries + x2 + exact error norms. grid (n,b,tc)=512.
__global__ void split_x_kernel(const float* __restrict__ x) {
    __shared__ float xs[128 * 33];
    int bi = blockIdx.x;
    int n  = bi >> 8;
    int b  = (bi >> 5) & 7;
    int tc = bi & 31;
    int tid = threadIdx.x;
    {
        int tt = tid & 31, dg = tid >> 5;
        const float* xp = x + ((size_t)b * CCH + (size_t)n * DDIM) * TLEN
                          + tc * 32 + tt;
        #pragma unroll
        for (int j = 0; j < 16; ++j) {
            int d = dg * 16 + j;
            xs[d * 33 + tt] = xp[(size_t)d * TLEN];
        }
    }
    __syncthreads();
    int tcol = tid >> 3;
    int sub  = tid & 7;
    int bt   = b * TLEN + tc * 32 + tcol;
    float x2 = 0.f, ex2 = 0.f, xh2 = 0.f;
    #pragma unroll
    for (int w = 0; w < 8; ++w) {
        float a  = xs[(sub * 16 + 2 * w) * 33 + tcol];
        float bb = xs[(sub * 16 + 2 * w + 1) * 33 + tcol];
        __half ha = __float2half_rn(a), hb = __float2half_rn(bb);
        float fa = __half2float(ha), fb = __half2float(hb);
        float ea = a - fa, eb = bb - fb;
        x2  += a * a + bb * bb;
        ex2 += ea * ea + eb * eb;
        xh2 += fa * fa + fb * fb;
        g_Ahat[(size_t)(n * BT + bt) * 64 + sub * 8 + w] = pack_h2(ha, hb);
    }
    #pragma unroll
    for (int o = 4; o; o >>= 1) {
        x2  += __shfl_xor_sync(0xFFFFFFFFu, x2, o);
        ex2 += __shfl_xor_sync(0xFFFFFFFFu, ex2, o);
        xh2 += __shfl_xor_sync(0xFFFFFFFFu, xh2, o);
    }
    if (sub == 0) {
        int q = n * BT + bt;
        g_x2[q] = x2; g_ex2[q] = ex2; g_xh2[q] = xh2;
    }
}

// ---------------------------------------------------------------------------
// vq_mma (f16, K=128): one CTA per (cb n, 128-query tile). 512 thr, 16 warps.
// A fragments in registers; B 64cw tiles double-buffered. Warp tile 16q x 32cw.
// Epilogue: per row per iter -> 8 scores, fminf tree -> ONE group-min,
// branchless top-6 of group-mins (zero branches in the hot loop).
// ---------------------------------------------------------------------------
#define ASTRIDE 272
#define BSTRIDE 272
#define SM_A    0
#define SM_B0   34816
#define SM_B1   52224
#define SM_MV   69632          // 128q x 48 floats (6 values x 8 lists)
#define SM_MK   94208          // 128q x 40 ints   (5 kbases x 8 lists)
#define SM_TOT  114688

__global__ void __launch_bounds__(512, 1)
vq_mma_kernel() {
    extern __shared__ char smraw[];
    const uint32_t sb = smem_u32(smraw);
    const int tid  = threadIdx.x;
    const int wid  = tid >> 5;
    const int lane = tid & 31;
    const int gq   = lane >> 2;
    const int tq   = lane & 3;
    const int mw   = wid >> 1;          // 0-7 (16q each)
    const int nw   = wid & 1;           // 0-1 (32cw each)
    const int n    = blockIdx.x >> 6;
    const int qbase = (blockIdx.x & 63) * 128;

    const char* bsrc = (const char*)g_Bhat + (size_t)n * KCB * 256;

    // prologue: group0 = A + Btile0 ; group1 = Btile1
    {
        const char* asrc = (const char*)g_Ahat + (size_t)(n * BT + qbase) * 256;
        #pragma unroll
        for (int it = 0; it < 4; ++it) {
            int c   = it * 512 + tid;
            int row = c >> 4, col = c & 15;
            cp_async16(sb + SM_A + row * ASTRIDE + col * 16,
                       asrc + (size_t)row * 256 + col * 16);
        }
        #pragma unroll
        for (int it = 0; it < 2; ++it) {
            int c   = it * 512 + tid;
            int row = c >> 4, col = c & 15;
            cp_async16(sb + SM_B0 + row * BSTRIDE + col * 16,
                       bsrc + (size_t)row * 256 + col * 16);
        }
        CP_COMMIT();
        #pragma unroll
        for (int it = 0; it < 2; ++it) {
            int c   = it * 512 + tid;
            int row = c >> 4, col = c & 15;
            cp_async16(sb + SM_B1 + row * BSTRIDE + col * 16,
                       bsrc + (size_t)(64 + row) * 256 + col * 16);
        }
        CP_COMMIT();
    }
    CP_WAIT1();
    __syncthreads();

    const uint32_t lmo = (uint32_t)(lane >> 4) * 16;
    const uint32_t aAddr = sb + SM_A +
        (uint32_t)(mw * 16 + (lane & 15)) * ASTRIDE + lmo;
    const uint32_t bAddrP[2] = {
        sb + SM_B0 + (uint32_t)(nw * 32 + (lane & 15)) * BSTRIDE + lmo,
        sb + SM_B1 + (uint32_t)(nw * 32 + (lane & 15)) * BSTRIDE + lmo };

    // hoist A fragments into registers (loop-invariant)
    uint32_t aF[8][4];
    #pragma unroll
    for (int ks = 0; ks < 8; ++ks)
        ldsm4(aF[ks][0], aF[ks][1], aF[ks][2], aF[ks][3], aAddr + ks * 32);

    // per-row top-6 of group-mins, explicit scalars
    float v1a, v2a, v3a, v4a, v5a, v6a, v1b, v2b, v3b, v4b, v5b, v6b;
    int   g1a, g2a, g3a, g4a, g5a, g1b, g2b, g3b, g4b, g5b;
    v1a = v2a = v3a = v4a = v5a = v6a = 3.4e38f;
    v1b = v2b = v3b = v4b = v5b = v6b = 3.4e38f;
    g1a = g2a = g3a = g4a = g5a = 0;
    g1b = g2b = g3b = g4b = g5b = 0;

    const int koff = nw * 32 + tq * 2;   // group kbase = iter*64 + koff

    for (int iter = 0; iter < 128; ++iter) {
        float acc[4][4];
        #pragma unroll
        for (int nt = 0; nt < 4; ++nt)
            #pragma unroll
            for (int j = 0; j < 4; ++j) acc[nt][j] = 0.f;

        const uint32_t bA = bAddrP[iter & 1];
        #pragma unroll
        for (int ks = 0; ks < 8; ++ks) {
            uint32_t b0x, b0y, b1x, b1y, b0z, b0w, b1z, b1w;
            ldsm4(b0x, b0y, b1x, b1y, bA + ks * 32);
            ldsm4(b0z, b0w, b1z, b1w, bA + 16 * BSTRIDE + ks * 32);
            mma_f16(acc[0], aF[ks][0], aF[ks][1], aF[ks][2], aF[ks][3], b0x, b1x);
            mma_f16(acc[1], aF[ks][0], aF[ks][1], aF[ks][2], aF[ks][3], b0y, b1y);
            mma_f16(acc[2], aF[ks][0], aF[ks][1], aF[ks][2], aF[ks][3], b0z, b1z);
            mma_f16(acc[3], aF[ks][0], aF[ks][1], aF[ks][2], aF[ks][3], b0w, b1w);
        }

        // epilogue (branch-free): 8 scores per row -> fminf tree -> 1 insert
        {
            const int kbw = iter * 64 + nw * 32;
            const float2 c0 = __ldg(reinterpret_cast<const float2*>(
                g_c2 + n * KCB + kbw + 0 + tq * 2));
            const float2 c1 = __ldg(reinterpret_cast<const float2*>(
                g_c2 + n * KCB + kbw + 8 + tq * 2));
            const float2 c2v = __ldg(reinterpret_cast<const float2*>(
                g_c2 + n * KCB + kbw + 16 + tq * 2));
            const float2 c3 = __ldg(reinterpret_cast<const float2*>(
                g_c2 + n * KCB + kbw + 24 + tq * 2));
            const int gi = iter * 64 + koff;
            // row a
            {
                float s0 = fmaf(acc[0][0], -2.0f, c0.x);
                float s1 = fmaf(acc[0][1], -2.0f, c0.y);
                float s2 = fmaf(acc[1][0], -2.0f, c1.x);
                float s3 = fmaf(acc[1][1], -2.0f, c1.y);
                float s4 = fmaf(acc[2][0], -2.0f, c2v.x);
                float s5 = fmaf(acc[2][1], -2.0f, c2v.y);
                float s6 = fmaf(acc[3][0], -2.0f, c3.x);
                float s7 = fmaf(acc[3][1], -2.0f, c3.y);
                float m = fminf(fminf(fminf(s0, s1), fminf(s2, s3)),
                                fminf(fminf(s4, s5), fminf(s6, s7)));
                BTOP6(m, gi, v1a, v2a, v3a, v4a, v5a, v6a,
                      g1a, g2a, g3a, g4a, g5a);
            }
            // row b
            {
                float s0 = fmaf(acc[0][2], -2.0f, c0.x);
                float s1 = fmaf(acc[0][3], -2.0f, c0.y);
                float s2 = fmaf(acc[1][2], -2.0f, c1.x);
                float s3 = fmaf(acc[1][3], -2.0f, c1.y);
                float s4 = fmaf(acc[2][2], -2.0f, c2v.x);
                float s5 = fmaf(acc[2][3], -2.0f, c2v.y);
                float s6 = fmaf(acc[3][2], -2.0f, c3.x);
                float s7 = fmaf(acc[3][3], -2.0f, c3.y);
                float m = fminf(fminf(fminf(s0, s1), fminf(s2, s3)),
                                fminf(fminf(s4, s5), fminf(s6, s7)));
                BTOP6(m, gi, v1b, v2b, v3b, v4b, v5b, v6b,
                      g1b, g2b, g3b, g4b, g5b);
            }
        }

        __syncthreads();
        if (iter + 2 < 128) {
            const char* src = bsrc + (size_t)(iter + 2) * 64 * 256;
            uint32_t dstb = sb + ((iter & 1) ? SM_B1 : SM_B0);
            #pragma unroll
            for (int it = 0; it < 2; ++it) {
                int c   = it * 512 + tid;
                int row = c >> 4, col = c & 15;
                cp_async16(dstb + row * BSTRIDE + col * 16,
                           src + (size_t)row * 256 + col * 16);
            }
            CP_COMMIT();
            CP_WAIT1();
        } else {
            CP_WAIT0();
        }
        __syncthreads();
    }

    // write per-thread lists: 8 lists per query, 6 values + 5 kbases each
    float* MV = (float*)(smraw + SM_MV);
    int*   MK = (int*)(smraw + SM_MK);
    {
        const int la  = nw * 4 + tq;
        const int qlA = mw * 16 + gq;
        const int vA  = qlA * 48 + la * 6;
        const int kA  = qlA * 40 + la * 5;
        MV[vA + 0] = v1a; MV[vA + 1] = v2a; MV[vA + 2] = v3a;
        MV[vA + 3] = v4a; MV[vA + 4] = v5a; MV[vA + 5] = v6a;
        MK[kA + 0] = g1a; MK[kA + 1] = g2a; MK[kA + 2] = g3a;
        MK[kA + 3] = g4a; MK[kA + 4] = g5a;
        const int qlB = mw * 16 + 8 + gq;
        const int vB  = qlB * 48 + la * 6;
        const int kB  = qlB * 40 + la * 5;
        MV[vB + 0] = v1b; MV[vB + 1] = v2b; MV[vB + 2] = v3b;
        MV[vB + 3] = v4b; MV[vB + 4] = v5b; MV[vB + 5] = v6b;
        MK[kB + 0] = g1b; MK[kB + 1] = g2b; MK[kB + 2] = g3b;
        MK[kB + 3] = g4b; MK[kB + 4] = g5b;
    }
    __syncthreads();

    // merge + computed rigorous window + group-candidate emission
    if (tid < 128) {
        const int q = n * BT + qbase + tid;
        float b1 = 3.4e38f;
        #pragma unroll
        for (int l = 0; l < 8; ++l)
            b1 = fminf(b1, MV[tid * 48 + l * 6]);
        float minv6 = 3.4e38f;
        #pragma unroll
        for (int l = 0; l < 8; ++l)
            minv6 = fminf(minv6, MV[tid * 48 + l * 6 + 5]);
        // win = 2*eps_q; eps_q = 2*(||ex||*maxc + ||xh||*maxec) + accum slack
        float cmax  = sqrtf(__int_as_float(g_c2max_bits[n]));
        float ecmax = sqrtf(__int_as_float(g_ec2max_bits[n]));
        float win = 4.0f * (sqrtf(g_ex2[q]) * cmax + sqrtf(g_xh2[q]) * ecmax)
                    + 2e-3f;
        float thr = b1 + win;

        int cnt;
        if (minv6 <= thr) {
            cnt = -1;           // some unlisted group could be in-window
        } else {
            cnt = 0;
            #pragma unroll
            for (int l = 0; l < 8; ++l) {
                #pragma unroll
                for (int j = 0; j < 5; ++j) {
                    float vv = MV[tid * 48 + l * 6 + j];
                    if (vv <= thr) {
                        if (cnt < NCANDG)
                            g_candk[q * NCANDG + cnt] = MK[tid * 40 + l * 5 + j];
                        ++cnt;
                    }
                }
            }
            if (cnt > NCANDG) cnt = -1;
        }
        g_candn[q] = cnt;
    }
}

// ---------------------------------------------------------------------------
// exact JAX-order d2 (same arithmetic as all passing rounds)
// ---------------------------------------------------------------------------
__device__ __forceinline__ float exact_d2(const float* __restrict__ x,
                                          const float* __restrict__ cb,
                                          int n, int b, int t, int bt, int k) {
    const float* xp = x + ((size_t)b * CCH + (size_t)n * DDIM) * TLEN + t;
    const float* cp = cb + ((size_t)n * KCB + (size_t)k) * DDIM;
    float xc = 0.f;
    #pragma unroll 8
    for (int d = 0; d < DDIM; ++d) xc = fmaf(xp[(size_t)d * TLEN], cp[d], xc);
    return __fadd_rn(__fsub_rn(g_x2[n * BT + bt], __fmul_rn(2.0f, xc)),
                     g_c2[n * KCB + k]);
}

// ---------------------------------------------------------------------------
// finalize: exact rescore of all 8 members of each in-window group
// ---------------------------------------------------------------------------
__global__ void finalize_kernel(const float* __restrict__ x,
                                const float* __restrict__ cb,
                                float* __restrict__ out) {
    int q = blockIdx.x * 256 + threadIdx.x;
    int n = q >> 13, bt = q & 8191, b = bt >> 10, t = bt & 1023;
    int cnt = g_candn[q];
    if (cnt < 0) {
        int pos = atomicAdd(&g_nflag, 1);
        g_flagq[pos] = q;
        return;
    }
    float bd = 3.4e38f;
    int   kf = 1 << 30;
    for (int i = 0; i < cnt; ++i) {
        int base = g_candk[q * NCANDG + i];
        #pragma unroll
        for (int m = 0; m < 8; ++m) {
            int k = base + (m >> 1) * 8 + (m & 1);
            float d = exact_d2(x, cb, n, b, t, bt, k);
            if (d < bd || (d == bd && k < kf)) { bd = d; kf = k; }
        }
    }
    g_idx[q] = kf;
    out[NQ + ((size_t)b * 2 + n) * TLEN + t] = (float)kf;
}

// ---------------------------------------------------------------------------
// fallback: PARALLEL exact full scan, one CTA per flagged query (strided)
// ---------------------------------------------------------------------------
__global__ void fallback_kernel(const float* __restrict__ x,
                                const float* __restrict__ cb,
                                float* __restrict__ out) {
    __shared__ float xq[128];
    __shared__ float sv[256];
    __shared__ int   sk[256];
    int nf = g_nflag;
    for (int i = blockIdx.x; i < nf; i += 256) {
        int q = g_flagq[i];
        int n = q >> 13, bt = q & 8191, b = bt >> 10, t = bt & 1023;
        if (threadIdx.x < 128)
            xq[threadIdx.x] = x[((size_t)b * CCH + (size_t)n * DDIM
                                 + threadIdx.x) * TLEN + t];
        __syncthreads();
        float x2v = g_x2[q];
        float bv = 3.4e38f;
        int   bk = 1 << 30;
        for (int j = 0; j < 32; ++j) {
            int k = j * 256 + threadIdx.x;
            const float* cp = cb + ((size_t)n * KCB + (size_t)k) * DDIM;
            float xc = 0.f;
            #pragma unroll 8
            for (int d = 0; d < DDIM; ++d) xc = fmaf(xq[d], cp[d], xc);
            float d2 = __fadd_rn(__fsub_rn(x2v, __fmul_rn(2.0f, xc)),
                                 g_c2[n * KCB + k]);
            if (d2 < bv || (d2 == bv && k < bk)) { bv = d2; bk = k; }
        }
        sv[threadIdx.x] = bv;
        sk[threadIdx.x] = bk;
        __syncthreads();
        for (int o = 128; o; o >>= 1) {
            if (threadIdx.x < o) {
                float ov = sv[threadIdx.x + o];
                int   ok = sk[threadIdx.x + o];
                if (ov < sv[threadIdx.x] ||
                    (ov == sv[threadIdx.x] && ok < sk[threadIdx.x])) {
                    sv[threadIdx.x] = ov; sk[threadIdx.x] = ok;
                }
            }
            __syncthreads();
        }
        if (threadIdx.x == 0) {
            g_idx[q] = sk[0];
            out[NQ + ((size_t)b * 2 + n) * TLEN + t] = (float)sk[0];
        }
        __syncthreads();
    }
}

// ---------------------------------------------------------------------------
// gather: coalesced quantized-output writes + commit-loss SSE
// ---------------------------------------------------------------------------
__global__ void gather_kernel(const float* __restrict__ x,
                              const float* __restrict__ cb,
                              float* __restrict__ out) {
    __shared__ float qs[128 * 33];
    __shared__ int   kq[32];
    __shared__ float red[8];
    int bi = blockIdx.x;
    int n  = bi >> 8;
    int b  = (bi >> 5) & 7;
    int tc = bi & 31;
    int tid = threadIdx.x;
    if (tid < 32) kq[tid] = g_idx[n * BT + b * TLEN + tc * 32 + tid];
    __syncthreads();
    #pragma unroll
    for (int j = 0; j < 16; ++j) {
        int idx = j * 256 + tid;
        int cw  = idx >> 7;
        int d   = idx & 127;
        qs[d * 33 + cw] = cb[((size_t)n * KCB + kq[cw]) * DDIM + d];
    }
    __syncthreads();
    float acc = 0.f;
    #pragma unroll
    for (int j = 0; j < 16; ++j) {
        int idx = j * 256 + tid;
        int d   = idx >> 5;
        int tt  = idx & 31;
        float w = qs[d * 33 + tt];
        size_t addr = ((size_t)b * CCH + (size_t)n * DDIM + d) * TLEN
                      + tc * 32 + tt;
        out[addr] = w;
        float df = x[addr] - w;
        acc += df * df;
    }
    #pragma unroll
    for (int o = 16; o; o >>= 1) acc += __shfl_down_sync(0xFFFFFFFFu, acc, o);
    if ((tid & 31) == 0) red[tid >> 5] = acc;
    __syncthreads();
    if (tid == 0) {
        float tot = 0.f;
        #pragma unroll
        for (int j = 0; j < 8; ++j) tot += red[j];
        atomicAdd(&g_sse, (double)tot);
    }
}

__global__ void fin_kernel(float* __restrict__ out) {
    out[NQ + NIDX] = (float)(0.25 * g_sse / (double)((long long)BT * DDIM));
}

// ---------------------------------------------------------------------------
extern "C" void kernel_launch(void* const* d_in, const int* in_sizes, int n_in,
                              void* d_out, int out_size) {
    const float* x  = (const float*)d_in[0];
    const float* cb = (const float*)d_in[1];
    float* out = (float*)d_out;

    cudaFuncSetAttribute(vq_mma_kernel,
                         cudaFuncAttributeMaxDynamicSharedMemorySize, SM_TOT);

    init_kernel<<<1, 32>>>();
    splitcb_kernel<<<2048, 256>>>(cb);
    split_x_kernel<<<512, 256>>>(x);
    vq_mma_kernel<<<128, 512, SM_TOT>>>();
    finalize_kernel<<<64, 256>>>(x, cb, out);
    fallback_kernel<<<256, 256>>>(x, cb, out);
    gather_kernel<<<512, 256>>>(x, cb, out);
    fin_kernel<<<1, 1>>>(out);
}

// round 15
// speedup vs baseline: 1.3917x; 1.3917x over previous
#include <cuda_runtime.h>
#include <cuda_fp16.h>
#include <cstdint>

// Problem constants
#define BT    8192
#define KCB   8192
#define DDIM  128
#define TLEN  1024
#define CCH   256
#define NQ    2097152
#define NIDX  16384
#define NCANDG 6            // max in-window GROUPS (8 k's each)

// ---------------------------------------------------------------------------
// Scratch (device globals; no allocation allowed)
// ---------------------------------------------------------------------------
__device__ __align__(16) unsigned g_Ahat[16384 * 64];  // f16x2 xh row (256B each)
__device__ __align__(16) unsigned g_Bhat[16384 * 64];  // f16x2 ch row (256B each)
__device__ float  g_c2[2 * KCB];
__device__ float  g_x2[2 * BT];
__device__ float  g_ex2[2 * BT];     // ||x - xh||^2  (exact)
__device__ float  g_xh2[2 * BT];     // ||xh||^2      (exact)
__device__ int    g_c2max_bits[2];   // max_k ||c_k||^2   (float bits)
__device__ int    g_ec2max_bits[2];  // max_k ||c-ch||^2  (float bits)
__device__ int    g_candk[2 * BT * NCANDG];   // group kbases
__device__ int    g_candn[2 * BT];   // group count, or -1 => fallback
__device__ int    g_idx[2 * BT];
__device__ int    g_flagq[2 * BT];
__device__ int    g_nflag;
__device__ double g_sse;

// ---------------------------------------------------------------------------
// PTX helpers (compute_103-legal only: ldmatrix / mma.sync / cp.async)
// ---------------------------------------------------------------------------
__device__ __forceinline__ uint32_t smem_u32(const void* p) {
    uint32_t a;
    asm("{ .reg .u64 t; cvta.to.shared.u64 t, %1; cvt.u32.u64 %0, t; }"
        : "=r"(a) : "l"(p));
    return a;
}
__device__ __forceinline__ void ldsm4(uint32_t& r0, uint32_t& r1,
                                      uint32_t& r2, uint32_t& r3, uint32_t a) {
    asm volatile("ldmatrix.sync.aligned.m8n8.x4.shared.b16 {%0,%1,%2,%3}, [%4];"
                 : "=r"(r0), "=r"(r1), "=r"(r2), "=r"(r3) : "r"(a));
}
__device__ __forceinline__ void mma_f16(float* d, uint32_t a0, uint32_t a1,
                                        uint32_t a2, uint32_t a3,
                                        uint32_t b0, uint32_t b1) {
    asm volatile(
        "mma.sync.aligned.m16n8k16.row.col.f32.f16.f16.f32 "
        "{%0,%1,%2,%3}, {%4,%5,%6,%7}, {%8,%9}, {%0,%1,%2,%3};"
        : "+f"(d[0]), "+f"(d[1]), "+f"(d[2]), "+f"(d[3])
        : "r"(a0), "r"(a1), "r"(a2), "r"(a3), "r"(b0), "r"(b1));
}
__device__ __forceinline__ void cp_async16(uint32_t dst, const void* src) {
    asm volatile("cp.async.cg.shared.global [%0], [%1], 16;"
                 :: "r"(dst), "l"(src) : "memory");
}
#define CP_COMMIT() asm volatile("cp.async.commit_group;" ::: "memory")
#define CP_WAIT0()  asm volatile("cp.async.wait_group 0;" ::: "memory")
#define CP_WAIT1()  asm volatile("cp.async.wait_group 1;" ::: "memory")

__device__ __forceinline__ unsigned pack_h2(__half a, __half b) {
    unsigned short ua = __half_as_ushort(a), ub = __half_as_ushort(b);
    return (unsigned)ua | ((unsigned)ub << 16);
}

// branchless top-6 insert of (s, gi): pure FSETP/SEL, no BSSY/BSYNC.
#define BTOP6(s, gi, V1, V2, V3, V4, V5, V6, G1, G2, G3, G4, G5) do {        \
    bool l1 = (s) < V1, l2 = (s) < V2, l3 = (s) < V3;                        \
    bool l4 = (s) < V4, l5 = (s) < V5, l6 = (s) < V6;                        \
    V6 = l6 ? (l5 ? V5 : (s)) : V6;                                          \
    V5 = l5 ? (l4 ? V4 : (s)) : V5;  G5 = l5 ? (l4 ? G4 : (gi)) : G5;        \
    V4 = l4 ? (l3 ? V3 : (s)) : V4;  G4 = l4 ? (l3 ? G3 : (gi)) : G4;        \
    V3 = l3 ? (l2 ? V2 : (s)) : V3;  G3 = l3 ? (l2 ? G2 : (gi)) : G3;        \
    V2 = l2 ? (l1 ? V1 : (s)) : V2;  G2 = l2 ? (l1 ? G1 : (gi)) : G2;        \
    V1 = l1 ? (s) : V1;              G1 = l1 ? (gi) : G1;                    \
} while (0)

// ---------------------------------------------------------------------------
__global__ void init_kernel() {
    if (blockIdx.x == 0 && threadIdx.x == 0) {
        g_sse = 0.0; g_nflag = 0;
        g_c2max_bits[0] = 0; g_c2max_bits[1] = 0;
        g_ec2max_bits[0] = 0; g_ec2max_bits[1] = 0;
    }
}

// splitcb: one warp per codeword row -> Bhat(f16 ch), c2, max c2, max ||ec||^2
__global__ void splitcb_kernel(const float* __restrict__ cb) {
    int row  = blockIdx.x * 8 + (threadIdx.x >> 5);
    int lane = threadIdx.x & 31;
    const float4 v = *reinterpret_cast<const float4*>(
        cb + (size_t)row * DDIM + lane * 4);
    __half h0 = __float2half_rn(v.x), h1 = __float2half_rn(v.y);
    __half h2 = __float2half_rn(v.z), h3 = __float2half_rn(v.w);
    g_Bhat[(size_t)row * 64 + 2 * lane]     = pack_h2(h0, h1);
    g_Bhat[(size_t)row * 64 + 2 * lane + 1] = pack_h2(h2, h3);
    float e0 = v.x - __half2float(h0), e1 = v.y - __half2float(h1);
    float e2 = v.z - __half2float(h2), e3 = v.w - __half2float(h3);
    float c2  = v.x * v.x + v.y * v.y + v.z * v.z + v.w * v.w;
    float ec2 = e0 * e0 + e1 * e1 + e2 * e2 + e3 * e3;
    #pragma unroll
    for (int o = 16; o; o >>= 1) {
        c2  += __shfl_down_sync(0xFFFFFFFFu, c2, o);
        ec2 += __shfl_down_sync(0xFFFFFFFFu, ec2, o);
    }
    if (lane == 0) {
        g_c2[row] = c2;
        atomicMax(&g_c2max_bits[row >> 13], __float_as_int(c2));
        atomicMax(&g_ec2max_bits[row >> 13], __float_as_int(ec2));
    }
}

// split_x: f16 quantize queries + x2 + exact error norms. grid (n,b,tc)=512.
__global__ void split_x_kernel(const float* __restrict__ x) {
    __shared__ float xs[128 * 33];
    int bi = blockIdx.x;
    int n  = bi >> 8;
    int b  = (bi >> 5) & 7;
    int tc = bi & 31;
    int tid = threadIdx.x;
    {
        int tt = tid & 31, dg = tid >> 5;
        const float* xp = x + ((size_t)b * CCH + (size_t)n * DDIM) * TLEN
                          + tc * 32 + tt;
        #pragma unroll
        for (int j = 0; j < 16; ++j) {
            int d = dg * 16 + j;
            xs[d * 33 + tt] = xp[(size_t)d * TLEN];
        }
    }
    __syncthreads();
    int tcol = tid >> 3;
    int sub  = tid & 7;
    int bt   = b * TLEN + tc * 32 + tcol;
    float x2 = 0.f, ex2 = 0.f, xh2 = 0.f;
    #pragma unroll
    for (int w = 0; w < 8; ++w) {
        float a  = xs[(sub * 16 + 2 * w) * 33 + tcol];
        float bb = xs[(sub * 16 + 2 * w + 1) * 33 + tcol];
        __half ha = __float2half_rn(a), hb = __float2half_rn(bb);
        float fa = __half2float(ha), fb = __half2float(hb);
        float ea = a - fa, eb = bb - fb;
        x2  += a * a + bb * bb;
        ex2 += ea * ea + eb * eb;
        xh2 += fa * fa + fb * fb;
        g_Ahat[(size_t)(n * BT + bt) * 64 + sub * 8 + w] = pack_h2(ha, hb);
    }
    #pragma unroll
    for (int o = 4; o; o >>= 1) {
        x2  += __shfl_xor_sync(0xFFFFFFFFu, x2, o);
        ex2 += __shfl_xor_sync(0xFFFFFFFFu, ex2, o);
        xh2 += __shfl_xor_sync(0xFFFFFFFFu, xh2, o);
    }
    if (sub == 0) {
        int q = n * BT + bt;
        g_x2[q] = x2; g_ex2[q] = ex2; g_xh2[q] = xh2;
    }
}

// ---------------------------------------------------------------------------
// vq_mma (f16, K=128) — UNCHANGED from round 14 (185.9 us, protected).
// ---------------------------------------------------------------------------
#define ASTRIDE 272
#define BSTRIDE 272
#define SM_A    0
#define SM_B0   34816
#define SM_B1   52224
#define SM_MV   69632          // 128q x 48 floats (6 values x 8 lists)
#define SM_MK   94208          // 128q x 40 ints   (5 kbases x 8 lists)
#define SM_TOT  114688

__global__ void __launch_bounds__(512, 1)
vq_mma_kernel() {
    extern __shared__ char smraw[];
    const uint32_t sb = smem_u32(smraw);
    const int tid  = threadIdx.x;
    const int wid  = tid >> 5;
    const int lane = tid & 31;
    const int gq   = lane >> 2;
    const int tq   = lane & 3;
    const int mw   = wid >> 1;          // 0-7 (16q each)
    const int nw   = wid & 1;           // 0-1 (32cw each)
    const int n    = blockIdx.x >> 6;
    const int qbase = (blockIdx.x & 63) * 128;

    const char* bsrc = (const char*)g_Bhat + (size_t)n * KCB * 256;

    // prologue: group0 = A + Btile0 ; group1 = Btile1
    {
        const char* asrc = (const char*)g_Ahat + (size_t)(n * BT + qbase) * 256;
        #pragma unroll
        for (int it = 0; it < 4; ++it) {
            int c   = it * 512 + tid;
            int row = c >> 4, col = c & 15;
            cp_async16(sb + SM_A + row * ASTRIDE + col * 16,
                       asrc + (size_t)row * 256 + col * 16);
        }
        #pragma unroll
        for (int it = 0; it < 2; ++it) {
            int c   = it * 512 + tid;
            int row = c >> 4, col = c & 15;
            cp_async16(sb + SM_B0 + row * BSTRIDE + col * 16,
                       bsrc + (size_t)row * 256 + col * 16);
        }
        CP_COMMIT();
        #pragma unroll
        for (int it = 0; it < 2; ++it) {
            int c   = it * 512 + tid;
            int row = c >> 4, col = c & 15;
            cp_async16(sb + SM_B1 + row * BSTRIDE + col * 16,
                       bsrc + (size_t)(64 + row) * 256 + col * 16);
        }
        CP_COMMIT();
    }
    CP_WAIT1();
    __syncthreads();

    const uint32_t lmo = (uint32_t)(lane >> 4) * 16;
    const uint32_t aAddr = sb + SM_A +
        (uint32_t)(mw * 16 + (lane & 15)) * ASTRIDE + lmo;
    const uint32_t bAddrP[2] = {
        sb + SM_B0 + (uint32_t)(nw * 32 + (lane & 15)) * BSTRIDE + lmo,
        sb + SM_B1 + (uint32_t)(nw * 32 + (lane & 15)) * BSTRIDE + lmo };

    // hoist A fragments into registers (loop-invariant)
    uint32_t aF[8][4];
    #pragma unroll
    for (int ks = 0; ks < 8; ++ks)
        ldsm4(aF[ks][0], aF[ks][1], aF[ks][2], aF[ks][3], aAddr + ks * 32);

    // per-row top-6 of group-mins, explicit scalars
    float v1a, v2a, v3a, v4a, v5a, v6a, v1b, v2b, v3b, v4b, v5b, v6b;
    int   g1a, g2a, g3a, g4a, g5a, g1b, g2b, g3b, g4b, g5b;
    v1a = v2a = v3a = v4a = v5a = v6a = 3.4e38f;
    v1b = v2b = v3b = v4b = v5b = v6b = 3.4e38f;
    g1a = g2a = g3a = g4a = g5a = 0;
    g1b = g2b = g3b = g4b = g5b = 0;

    const int koff = nw * 32 + tq * 2;   // group kbase = iter*64 + koff

    for (int iter = 0; iter < 128; ++iter) {
        float acc[4][4];
        #pragma unroll
        for (int nt = 0; nt < 4; ++nt)
            #pragma unroll
            for (int j = 0; j < 4; ++j) acc[nt][j] = 0.f;

        const uint32_t bA = bAddrP[iter & 1];
        #pragma unroll
        for (int ks = 0; ks < 8; ++ks) {
            uint32_t b0x, b0y, b1x, b1y, b0z, b0w, b1z, b1w;
            ldsm4(b0x, b0y, b1x, b1y, bA + ks * 32);
            ldsm4(b0z, b0w, b1z, b1w, bA + 16 * BSTRIDE + ks * 32);
            mma_f16(acc[0], aF[ks][0], aF[ks][1], aF[ks][2], aF[ks][3], b0x, b1x);
            mma_f16(acc[1], aF[ks][0], aF[ks][1], aF[ks][2], aF[ks][3], b0y, b1y);
            mma_f16(acc[2], aF[ks][0], aF[ks][1], aF[ks][2], aF[ks][3], b0z, b1z);
            mma_f16(acc[3], aF[ks][0], aF[ks][1], aF[ks][2], aF[ks][3], b0w, b1w);
        }

        // epilogue (branch-free): 8 scores per row -> fminf tree -> 1 insert
        {
            const int kbw = iter * 64 + nw * 32;
            const float2 c0 = __ldg(reinterpret_cast<const float2*>(
                g_c2 + n * KCB + kbw + 0 + tq * 2));
            const float2 c1 = __ldg(reinterpret_cast<const float2*>(
                g_c2 + n * KCB + kbw + 8 + tq * 2));
            const float2 c2v = __ldg(reinterpret_cast<const float2*>(
                g_c2 + n * KCB + kbw + 16 + tq * 2));
            const float2 c3 = __ldg(reinterpret_cast<const float2*>(
                g_c2 + n * KCB + kbw + 24 + tq * 2));
            const int gi = iter * 64 + koff;
            {
                float s0 = fmaf(acc[0][0], -2.0f, c0.x);
                float s1 = fmaf(acc[0][1], -2.0f, c0.y);
                float s2 = fmaf(acc[1][0], -2.0f, c1.x);
                float s3 = fmaf(acc[1][1], -2.0f, c1.y);
                float s4 = fmaf(acc[2][0], -2.0f, c2v.x);
                float s5 = fmaf(acc[2][1], -2.0f, c2v.y);
                float s6 = fmaf(acc[3][0], -2.0f, c3.x);
                float s7 = fmaf(acc[3][1], -2.0f, c3.y);
                float m = fminf(fminf(fminf(s0, s1), fminf(s2, s3)),
                                fminf(fminf(s4, s5), fminf(s6, s7)));
                BTOP6(m, gi, v1a, v2a, v3a, v4a, v5a, v6a,
                      g1a, g2a, g3a, g4a, g5a);
            }
            {
                float s0 = fmaf(acc[0][2], -2.0f, c0.x);
                float s1 = fmaf(acc[0][3], -2.0f, c0.y);
                float s2 = fmaf(acc[1][2], -2.0f, c1.x);
                float s3 = fmaf(acc[1][3], -2.0f, c1.y);
                float s4 = fmaf(acc[2][2], -2.0f, c2v.x);
                float s5 = fmaf(acc[2][3], -2.0f, c2v.y);
                float s6 = fmaf(acc[3][2], -2.0f, c3.x);
                float s7 = fmaf(acc[3][3], -2.0f, c3.y);
                float m = fminf(fminf(fminf(s0, s1), fminf(s2, s3)),
                                fminf(fminf(s4, s5), fminf(s6, s7)));
                BTOP6(m, gi, v1b, v2b, v3b, v4b, v5b, v6b,
                      g1b, g2b, g3b, g4b, g5b);
            }
        }

        __syncthreads();
        if (iter + 2 < 128) {
            const char* src = bsrc + (size_t)(iter + 2) * 64 * 256;
            uint32_t dstb = sb + ((iter & 1) ? SM_B1 : SM_B0);
            #pragma unroll
            for (int it = 0; it < 2; ++it) {
                int c   = it * 512 + tid;
                int row = c >> 4, col = c & 15;
                cp_async16(dstb + row * BSTRIDE + col * 16,
                           src + (size_t)row * 256 + col * 16);
            }
            CP_COMMIT();
            CP_WAIT1();
        } else {
            CP_WAIT0();
        }
        __syncthreads();
    }

    // write per-thread lists: 8 lists per query, 6 values + 5 kbases each
    float* MV = (float*)(smraw + SM_MV);
    int*   MK = (int*)(smraw + SM_MK);
    {
        const int la  = nw * 4 + tq;
        const int qlA = mw * 16 + gq;
        const int vA  = qlA * 48 + la * 6;
        const int kA  = qlA * 40 + la * 5;
        MV[vA + 0] = v1a; MV[vA + 1] = v2a; MV[vA + 2] = v3a;
        MV[vA + 3] = v4a; MV[vA + 4] = v5a; MV[vA + 5] = v6a;
        MK[kA + 0] = g1a; MK[kA + 1] = g2a; MK[kA + 2] = g3a;
        MK[kA + 3] = g4a; MK[kA + 4] = g5a;
        const int qlB = mw * 16 + 8 + gq;
        const int vB  = qlB * 48 + la * 6;
        const int kB  = qlB * 40 + la * 5;
        MV[vB + 0] = v1b; MV[vB + 1] = v2b; MV[vB + 2] = v3b;
        MV[vB + 3] = v4b; MV[vB + 4] = v5b; MV[vB + 5] = v6b;
        MK[kB + 0] = g1b; MK[kB + 1] = g2b; MK[kB + 2] = g3b;
        MK[kB + 3] = g4b; MK[kB + 4] = g5b;
    }
    __syncthreads();

    // merge + computed rigorous window + group-candidate emission
    if (tid < 128) {
        const int q = n * BT + qbase + tid;
        float b1 = 3.4e38f;
        #pragma unroll
        for (int l = 0; l < 8; ++l)
            b1 = fminf(b1, MV[tid * 48 + l * 6]);
        float minv6 = 3.4e38f;
        #pragma unroll
        for (int l = 0; l < 8; ++l)
            minv6 = fminf(minv6, MV[tid * 48 + l * 6 + 5]);
        float cmax  = sqrtf(__int_as_float(g_c2max_bits[n]));
        float ecmax = sqrtf(__int_as_float(g_ec2max_bits[n]));
        float win = 4.0f * (sqrtf(g_ex2[q]) * cmax + sqrtf(g_xh2[q]) * ecmax)
                    + 2e-3f;
        float thr = b1 + win;

        int cnt;
        if (minv6 <= thr) {
            cnt = -1;
        } else {
            cnt = 0;
            #pragma unroll
            for (int l = 0; l < 8; ++l) {
                #pragma unroll
                for (int j = 0; j < 5; ++j) {
                    float vv = MV[tid * 48 + l * 6 + j];
                    if (vv <= thr) {
                        if (cnt < NCANDG)
                            g_candk[q * NCANDG + cnt] = MK[tid * 40 + l * 5 + j];
                        ++cnt;
                    }
                }
            }
            if (cnt > NCANDG) cnt = -1;
        }
        g_candn[q] = cnt;
    }
}

// ---------------------------------------------------------------------------
// exact JAX-order d2 (same arithmetic as all passing rounds)
// ---------------------------------------------------------------------------
__device__ __forceinline__ float exact_d2(const float* __restrict__ x,
                                          const float* __restrict__ cb,
                                          int n, int b, int t, int bt, int k) {
    const float* xp = x + ((size_t)b * CCH + (size_t)n * DDIM) * TLEN + t;
    const float* cp = cb + ((size_t)n * KCB + (size_t)k) * DDIM;
    float xc = 0.f;
    #pragma unroll 8
    for (int d = 0; d < DDIM; ++d) xc = fmaf(xp[(size_t)d * TLEN], cp[d], xc);
    return __fadd_rn(__fsub_rn(g_x2[n * BT + bt], __fmul_rn(2.0f, xc)),
                     g_c2[n * KCB + k]);
}

// ---------------------------------------------------------------------------
// finalize: 8 LANES PER QUERY. Lane m rescores member m of each candidate
// group; 3-step shfl_xor segment-reduce (aligned 8-lane groups); no early
// returns (warp stays converged for the shuffles).
// grid 512 x 256: 32 queries per block.
// ---------------------------------------------------------------------------
__global__ void finalize_kernel(const float* __restrict__ x,
                                const float* __restrict__ cb,
                                float* __restrict__ out) {
    int q = blockIdx.x * 32 + (threadIdx.x >> 3);
    int m = threadIdx.x & 7;
    int n = q >> 13, bt = q & 8191, b = bt >> 10, t = bt & 1023;
    int cnt = g_candn[q];
    int work = (cnt < 0) ? 0 : cnt;

    float bd = 3.4e38f;
    int   kf = 1 << 30;
    for (int i = 0; i < work; ++i) {
        int base = g_candk[q * NCANDG + i];
        int k = base + (m >> 1) * 8 + (m & 1);
        float d = exact_d2(x, cb, n, b, t, bt, k);
        if (d < bd || (d == bd && k < kf)) { bd = d; kf = k; }
    }
    // segment reduce over the aligned 8-lane group
    #pragma unroll
    for (int o = 4; o; o >>= 1) {
        float ov = __shfl_xor_sync(0xFFFFFFFFu, bd, o);
        int   ok = __shfl_xor_sync(0xFFFFFFFFu, kf, o);
        if (ov < bd || (ov == bd && ok < kf)) { bd = ov; kf = ok; }
    }
    if (m == 0) {
        if (cnt < 0) {
            int pos = atomicAdd(&g_nflag, 1);
            g_flagq[pos] = q;
        } else {
            g_idx[q] = kf;
            out[NQ + ((size_t)b * 2 + n) * TLEN + t] = (float)kf;
        }
    }
}

// ---------------------------------------------------------------------------
// fallback: PARALLEL exact full scan, one CTA per flagged query (strided)
// ---------------------------------------------------------------------------
__global__ void fallback_kernel(const float* __restrict__ x,
                                const float* __restrict__ cb,
                                float* __restrict__ out) {
    __shared__ float xq[128];
    __shared__ float sv[256];
    __shared__ int   sk[256];
    int nf = g_nflag;
    for (int i = blockIdx.x; i < nf; i += 256) {
        int q = g_flagq[i];
        int n = q >> 13, bt = q & 8191, b = bt >> 10, t = bt & 1023;
        if (threadIdx.x < 128)
            xq[threadIdx.x] = x[((size_t)b * CCH + (size_t)n * DDIM
                                 + threadIdx.x) * TLEN + t];
        __syncthreads();
        float x2v = g_x2[q];
        float bv = 3.4e38f;
        int   bk = 1 << 30;
        for (int j = 0; j < 32; ++j) {
            int k = j * 256 + threadIdx.x;
            const float* cp = cb + ((size_t)n * KCB + (size_t)k) * DDIM;
            float xc = 0.f;
            #pragma unroll 8
            for (int d = 0; d < DDIM; ++d) xc = fmaf(xq[d], cp[d], xc);
            float d2 = __fadd_rn(__fsub_rn(x2v, __fmul_rn(2.0f, xc)),
                                 g_c2[n * KCB + k]);
            if (d2 < bv || (d2 == bv && k < bk)) { bv = d2; bk = k; }
        }
        sv[threadIdx.x] = bv;
        sk[threadIdx.x] = bk;
        __syncthreads();
        for (int o = 128; o; o >>= 1) {
            if (threadIdx.x < o) {
                float ov = sv[threadIdx.x + o];
                int   ok = sk[threadIdx.x + o];
                if (ov < sv[threadIdx.x] ||
                    (ov == sv[threadIdx.x] && ok < sk[threadIdx.x])) {
                    sv[threadIdx.x] = ov; sk[threadIdx.x] = ok;
                }
            }
            __syncthreads();
        }
        if (threadIdx.x == 0) {
            g_idx[q] = sk[0];
            out[NQ + ((size_t)b * 2 + n) * TLEN + t] = (float)sk[0];
        }
        __syncthreads();
    }
}

// ---------------------------------------------------------------------------
// gather: coalesced quantized-output writes + commit-loss SSE
// ---------------------------------------------------------------------------
__global__ void gather_kernel(const float* __restrict__ x,
                              const float* __restrict__ cb,
                              float* __restrict__ out) {
    __shared__ float qs[128 * 33];
    __shared__ int   kq[32];
    __shared__ float red[8];
    int bi = blockIdx.x;
    int n  = bi >> 8;
    int b  = (bi >> 5) & 7;
    int tc = bi & 31;
    int tid = threadIdx.x;
    if (tid < 32) kq[tid] = g_idx[n * BT + b * TLEN + tc * 32 + tid];
    __syncthreads();
    #pragma unroll
    for (int j = 0; j < 16; ++j) {
        int idx = j * 256 + tid;
        int cw  = idx >> 7;
        int d   = idx & 127;
        qs[d * 33 + cw] = cb[((size_t)n * KCB + kq[cw]) * DDIM + d];
    }
    __syncthreads();
    float acc = 0.f;
    #pragma unroll
    for (int j = 0; j < 16; ++j) {
        int idx = j * 256 + tid;
        int d   = idx >> 5;
        int tt  = idx & 31;
        float w = qs[d * 33 + tt];
        size_t addr = ((size_t)b * CCH + (size_t)n * DDIM + d) * TLEN
                      + tc * 32 + tt;
        out[addr] = w;
        float df = x[addr] - w;
        acc += df * df;
    }
    #pragma unroll
    for (int o = 16; o; o >>= 1) acc += __shfl_down_sync(0xFFFFFFFFu, acc, o);
    if ((tid & 31) == 0) red[tid >> 5] = acc;
    __syncthreads();
    if (tid == 0) {
        float tot = 0.f;
        #pragma unroll
        for (int j = 0; j < 8; ++j) tot += red[j];
        atomicAdd(&g_sse, (double)tot);
    }
}

__global__ void fin_kernel(float* __restrict__ out) {
    out[NQ + NIDX] = (float)(0.25 * g_sse / (double)((long long)BT * DDIM));
}

// ---------------------------------------------------------------------------
extern "C" void kernel_launch(void* const* d_in, const int* in_sizes, int n_in,
                              void* d_out, int out_size) {
    const float* x  = (const float*)d_in[0];
    const float* cb = (const float*)d_in[1];
    float* out = (float*)d_out;

    cudaFuncSetAttribute(vq_mma_kernel,
                         cudaFuncAttributeMaxDynamicSharedMemorySize, SM_TOT);

    init_kernel<<<1, 32>>>();
    splitcb_kernel<<<2048, 256>>>(cb);
    split_x_kernel<<<512, 256>>>(x);
    vq_mma_kernel<<<128, 512, SM_TOT>>>();
    finalize_kernel<<<512, 256>>>(x, cb, out);
    fallback_kernel<<<256, 256>>>(x, cb, out);
    gather_kernel<<<512, 256>>>(x, cb, out);
    fin_kernel<<<1, 1>>>(out);
}

// round 16
// speedup vs baseline: 1.5422x; 1.1081x over previous
#include <cuda_runtime.h>
#include <cuda_fp16.h>
#include <cstdint>

// Problem constants
#define BT    8192
#define KCB   8192
#define DDIM  128
#define TLEN  1024
#define CCH   256
#define NQ    2097152
#define NIDX  16384
#define NCANDG 6            // max in-window GROUPS (8 k's each)

// ---------------------------------------------------------------------------
// Scratch (device globals; no allocation allowed)
// ---------------------------------------------------------------------------
__device__ __align__(16) unsigned g_Ahat[16384 * 64];  // f16x2 xh row (256B each)
__device__ __align__(16) unsigned g_Bhat[16384 * 64];  // f16x2 ch row (256B each)
__device__ float  g_c2[2 * KCB];
__device__ float  g_x2[2 * BT];
__device__ float  g_ex2[2 * BT];     // ||x - xh||^2  (exact)
__device__ float  g_xh2[2 * BT];     // ||xh||^2      (exact)
__device__ int    g_c2max_bits[2];   // max_k ||c_k||^2   (float bits)
__device__ int    g_ec2max_bits[2];  // max_k ||c-ch||^2  (float bits)
__device__ int    g_candk[2 * BT * NCANDG];   // group kbases
__device__ int    g_candn[2 * BT];   // group count, or -1 => fallback
__device__ int    g_idx[2 * BT];
__device__ int    g_flagq[2 * BT];
__device__ int    g_nflag;
__device__ double g_sse;

// ---------------------------------------------------------------------------
// PTX helpers (compute_103-legal only: ldmatrix / mma.sync / cp.async)
// ---------------------------------------------------------------------------
__device__ __forceinline__ uint32_t smem_u32(const void* p) {
    uint32_t a;
    asm("{ .reg .u64 t; cvta.to.shared.u64 t, %1; cvt.u32.u64 %0, t; }"
        : "=r"(a) : "l"(p));
    return a;
}
__device__ __forceinline__ void ldsm4(uint32_t& r0, uint32_t& r1,
                                      uint32_t& r2, uint32_t& r3, uint32_t a) {
    asm volatile("ldmatrix.sync.aligned.m8n8.x4.shared.b16 {%0,%1,%2,%3}, [%4];"
                 : "=r"(r0), "=r"(r1), "=r"(r2), "=r"(r3) : "r"(a));
}
__device__ __forceinline__ void mma_f16(float* d, uint32_t a0, uint32_t a1,
                                        uint32_t a2, uint32_t a3,
                                        uint32_t b0, uint32_t b1) {
    asm volatile(
        "mma.sync.aligned.m16n8k16.row.col.f32.f16.f16.f32 "
        "{%0,%1,%2,%3}, {%4,%5,%6,%7}, {%8,%9}, {%0,%1,%2,%3};"
        : "+f"(d[0]), "+f"(d[1]), "+f"(d[2]), "+f"(d[3])
        : "r"(a0), "r"(a1), "r"(a2), "r"(a3), "r"(b0), "r"(b1));
}
__device__ __forceinline__ void cp_async16(uint32_t dst, const void* src) {
    asm volatile("cp.async.cg.shared.global [%0], [%1], 16;"
                 :: "r"(dst), "l"(src) : "memory");
}
#define CP_COMMIT() asm volatile("cp.async.commit_group;" ::: "memory")
#define CP_WAIT0()  asm volatile("cp.async.wait_group 0;" ::: "memory")
#define CP_WAIT1()  asm volatile("cp.async.wait_group 1;" ::: "memory")

__device__ __forceinline__ unsigned pack_h2(__half a, __half b) {
    unsigned short ua = __half_as_ushort(a), ub = __half_as_ushort(b);
    return (unsigned)ua | ((unsigned)ub << 16);
}

// branchless top-6 insert of (s, gi): pure FSETP/SEL, no BSSY/BSYNC.
#define BTOP6(s, gi, V1, V2, V3, V4, V5, V6, G1, G2, G3, G4, G5) do {        \
    bool l1 = (s) < V1, l2 = (s) < V2, l3 = (s) < V3;                        \
    bool l4 = (s) < V4, l5 = (s) < V5, l6 = (s) < V6;                        \
    V6 = l6 ? (l5 ? V5 : (s)) : V6;                                          \
    V5 = l5 ? (l4 ? V4 : (s)) : V5;  G5 = l5 ? (l4 ? G4 : (gi)) : G5;        \
    V4 = l4 ? (l3 ? V3 : (s)) : V4;  G4 = l4 ? (l3 ? G3 : (gi)) : G4;        \
    V3 = l3 ? (l2 ? V2 : (s)) : V3;  G3 = l3 ? (l2 ? G2 : (gi)) : G3;        \
    V2 = l2 ? (l1 ? V1 : (s)) : V2;  G2 = l2 ? (l1 ? G1 : (gi)) : G2;        \
    V1 = l1 ? (s) : V1;              G1 = l1 ? (gi) : G1;                    \
} while (0)

// ---------------------------------------------------------------------------
__global__ void init_kernel() {
    if (blockIdx.x == 0 && threadIdx.x == 0) {
        g_sse = 0.0; g_nflag = 0;
        g_c2max_bits[0] = 0; g_c2max_bits[1] = 0;
        g_ec2max_bits[0] = 0; g_ec2max_bits[1] = 0;
    }
}

// splitcb: one warp per codeword row -> Bhat(f16 ch), c2, max c2, max ||ec||^2
__global__ void splitcb_kernel(const float* __restrict__ cb) {
    int row  = blockIdx.x * 8 + (threadIdx.x >> 5);
    int lane = threadIdx.x & 31;
    const float4 v = *reinterpret_cast<const float4*>(
        cb + (size_t)row * DDIM + lane * 4);
    __half h0 = __float2half_rn(v.x), h1 = __float2half_rn(v.y);
    __half h2 = __float2half_rn(v.z), h3 = __float2half_rn(v.w);
    g_Bhat[(size_t)row * 64 + 2 * lane]     = pack_h2(h0, h1);
    g_Bhat[(size_t)row * 64 + 2 * lane + 1] = pack_h2(h2, h3);
    float e0 = v.x - __half2float(h0), e1 = v.y - __half2float(h1);
    float e2 = v.z - __half2float(h2), e3 = v.w - __half2float(h3);
    float c2  = v.x * v.x + v.y * v.y + v.z * v.z + v.w * v.w;
    float ec2 = e0 * e0 + e1 * e1 + e2 * e2 + e3 * e3;
    #pragma unroll
    for (int o = 16; o; o >>= 1) {
        c2  += __shfl_down_sync(0xFFFFFFFFu, c2, o);
        ec2 += __shfl_down_sync(0xFFFFFFFFu, ec2, o);
    }
    if (lane == 0) {
        g_c2[row] = c2;
        atomicMax(&g_c2max_bits[row >> 13], __float_as_int(c2));
        atomicMax(&g_ec2max_bits[row >> 13], __float_as_int(ec2));
    }
}

// split_x: f16 quantize queries + x2 + exact error norms. grid (n,b,tc)=512.
__global__ void split_x_kernel(const float* __restrict__ x) {
    __shared__ float xs[128 * 33];
    int bi = blockIdx.x;
    int n  = bi >> 8;
    int b  = (bi >> 5) & 7;
    int tc = bi & 31;
    int tid = threadIdx.x;
    {
        int tt = tid & 31, dg = tid >> 5;
        const float* xp = x + ((size_t)b * CCH + (size_t)n * DDIM) * TLEN
                          + tc * 32 + tt;
        #pragma unroll
        for (int j = 0; j < 16; ++j) {
            int d = dg * 16 + j;
            xs[d * 33 + tt] = xp[(size_t)d * TLEN];
        }
    }
    __syncthreads();
    int tcol = tid >> 3;
    int sub  = tid & 7;
    int bt   = b * TLEN + tc * 32 + tcol;
    float x2 = 0.f, ex2 = 0.f, xh2 = 0.f;
    #pragma unroll
    for (int w = 0; w < 8; ++w) {
        float a  = xs[(sub * 16 + 2 * w) * 33 + tcol];
        float bb = xs[(sub * 16 + 2 * w + 1) * 33 + tcol];
        __half ha = __float2half_rn(a), hb = __float2half_rn(bb);
        float fa = __half2float(ha), fb = __half2float(hb);
        float ea = a - fa, eb = bb - fb;
        x2  += a * a + bb * bb;
        ex2 += ea * ea + eb * eb;
        xh2 += fa * fa + fb * fb;
        g_Ahat[(size_t)(n * BT + bt) * 64 + sub * 8 + w] = pack_h2(ha, hb);
    }
    #pragma unroll
    for (int o = 4; o; o >>= 1) {
        x2  += __shfl_xor_sync(0xFFFFFFFFu, x2, o);
        ex2 += __shfl_xor_sync(0xFFFFFFFFu, ex2, o);
        xh2 += __shfl_xor_sync(0xFFFFFFFFu, xh2, o);
    }
    if (sub == 0) {
        int q = n * BT + bt;
        g_x2[q] = x2; g_ex2[q] = ex2; g_xh2[q] = xh2;
    }
}

// ---------------------------------------------------------------------------
// vq_mma (f16, K=128): one CTA per (cb n, 128-query tile). 256 thr, 8 warps
// (4 mw x 2 nw). Warp tile 32q x 32cw: 2 A m-frags in regs, B fragments feed
// 8 mma each (2x reuse vs round 15), 64-deep mma chain per iter for latency
// hiding. Branch-free group-min epilogue, 4 q-rows per thread.
// ---------------------------------------------------------------------------
#define ASTRIDE 272
#define BSTRIDE 272
#define SM_A    0
#define SM_B0   34816
#define SM_B1   52224
#define SM_MV   69632          // 128q x 48 floats (6 values x 8 lists)
#define SM_MK   94208          // 128q x 40 ints   (5 kbases x 8 lists)
#define SM_TOT  114688

__global__ void __launch_bounds__(256, 1)
vq_mma_kernel() {
    extern __shared__ char smraw[];
    const uint32_t sb = smem_u32(smraw);
    const int tid  = threadIdx.x;
    const int wid  = tid >> 5;
    const int lane = tid & 31;
    const int gq   = lane >> 2;
    const int tq   = lane & 3;
    const int mw   = wid >> 1;          // 0-3 (32q each)
    const int nw   = wid & 1;           // 0-1 (32cw each)
    const int n    = blockIdx.x >> 6;
    const int qbase = (blockIdx.x & 63) * 128;

    const char* bsrc = (const char*)g_Bhat + (size_t)n * KCB * 256;

    // prologue: group0 = A + Btile0 ; group1 = Btile1
    {
        const char* asrc = (const char*)g_Ahat + (size_t)(n * BT + qbase) * 256;
        #pragma unroll
        for (int it = 0; it < 8; ++it) {
            int c   = it * 256 + tid;
            int row = c >> 4, col = c & 15;
            cp_async16(sb + SM_A + row * ASTRIDE + col * 16,
                       asrc + (size_t)row * 256 + col * 16);
        }
        #pragma unroll
        for (int it = 0; it < 4; ++it) {
            int c   = it * 256 + tid;
            int row = c >> 4, col = c & 15;
            cp_async16(sb + SM_B0 + row * BSTRIDE + col * 16,
                       bsrc + (size_t)row * 256 + col * 16);
        }
        CP_COMMIT();
        #pragma unroll
        for (int it = 0; it < 4; ++it) {
            int c   = it * 256 + tid;
            int row = c >> 4, col = c & 15;
            cp_async16(sb + SM_B1 + row * BSTRIDE + col * 16,
                       bsrc + (size_t)(64 + row) * 256 + col * 16);
        }
        CP_COMMIT();
    }
    CP_WAIT1();
    __syncthreads();

    const uint32_t lmo = (uint32_t)(lane >> 4) * 16;
    const uint32_t aAddr0 = sb + SM_A +
        (uint32_t)(mw * 32 + (lane & 15)) * ASTRIDE + lmo;
    const uint32_t aAddr1 = aAddr0 + 16 * ASTRIDE;
    const uint32_t bAddrP[2] = {
        sb + SM_B0 + (uint32_t)(nw * 32 + (lane & 15)) * BSTRIDE + lmo,
        sb + SM_B1 + (uint32_t)(nw * 32 + (lane & 15)) * BSTRIDE + lmo };

    // hoist BOTH A m-fragments into registers (loop-invariant)
    uint32_t aF0[8][4], aF1[8][4];
    #pragma unroll
    for (int ks = 0; ks < 8; ++ks) {
        ldsm4(aF0[ks][0], aF0[ks][1], aF0[ks][2], aF0[ks][3], aAddr0 + ks * 32);
        ldsm4(aF1[ks][0], aF1[ks][1], aF1[ks][2], aF1[ks][3], aAddr1 + ks * 32);
    }

    // per-thread top-6 of group-mins for 4 q-rows (constant-indexed arrays)
    float v[4][6];
    int   g[4][5];
    #pragma unroll
    for (int r = 0; r < 4; ++r) {
        #pragma unroll
        for (int j = 0; j < 6; ++j) v[r][j] = 3.4e38f;
        #pragma unroll
        for (int j = 0; j < 5; ++j) g[r][j] = 0;
    }

    const int koff = nw * 32 + tq * 2;

    for (int iter = 0; iter < 128; ++iter) {
        float acc[2][4][4];
        #pragma unroll
        for (int fr = 0; fr < 2; ++fr)
            #pragma unroll
            for (int nt = 0; nt < 4; ++nt)
                #pragma unroll
                for (int j = 0; j < 4; ++j) acc[fr][nt][j] = 0.f;

        const uint32_t bA = bAddrP[iter & 1];
        #pragma unroll
        for (int ks = 0; ks < 8; ++ks) {
            uint32_t b0x, b0y, b1x, b1y, b0z, b0w, b1z, b1w;
            ldsm4(b0x, b0y, b1x, b1y, bA + ks * 32);
            ldsm4(b0z, b0w, b1z, b1w, bA + 16 * BSTRIDE + ks * 32);
            mma_f16(acc[0][0], aF0[ks][0], aF0[ks][1], aF0[ks][2], aF0[ks][3], b0x, b1x);
            mma_f16(acc[0][1], aF0[ks][0], aF0[ks][1], aF0[ks][2], aF0[ks][3], b0y, b1y);
            mma_f16(acc[0][2], aF0[ks][0], aF0[ks][1], aF0[ks][2], aF0[ks][3], b0z, b1z);
            mma_f16(acc[0][3], aF0[ks][0], aF0[ks][1], aF0[ks][2], aF0[ks][3], b0w, b1w);
            mma_f16(acc[1][0], aF1[ks][0], aF1[ks][1], aF1[ks][2], aF1[ks][3], b0x, b1x);
            mma_f16(acc[1][1], aF1[ks][0], aF1[ks][1], aF1[ks][2], aF1[ks][3], b0y, b1y);
            mma_f16(acc[1][2], aF1[ks][0], aF1[ks][1], aF1[ks][2], aF1[ks][3], b0z, b1z);
            mma_f16(acc[1][3], aF1[ks][0], aF1[ks][1], aF1[ks][2], aF1[ks][3], b0w, b1w);
        }

        // epilogue (branch-free): per row 8 scores -> fminf tree -> 1 insert
        {
            const int kbw = iter * 64 + nw * 32;
            const float2 c0 = __ldg(reinterpret_cast<const float2*>(
                g_c2 + n * KCB + kbw + 0 + tq * 2));
            const float2 c1 = __ldg(reinterpret_cast<const float2*>(
                g_c2 + n * KCB + kbw + 8 + tq * 2));
            const float2 c2v = __ldg(reinterpret_cast<const float2*>(
                g_c2 + n * KCB + kbw + 16 + tq * 2));
            const float2 c3 = __ldg(reinterpret_cast<const float2*>(
                g_c2 + n * KCB + kbw + 24 + tq * 2));
            const int gi = iter * 64 + koff;
            #pragma unroll
            for (int fr = 0; fr < 2; ++fr) {
                #pragma unroll
                for (int half = 0; half < 2; ++half) {
                    const int r = fr * 2 + half;
                    float s0 = fmaf(acc[fr][0][half * 2 + 0], -2.0f, c0.x);
                    float s1 = fmaf(acc[fr][0][half * 2 + 1], -2.0f, c0.y);
                    float s2 = fmaf(acc[fr][1][half * 2 + 0], -2.0f, c1.x);
                    float s3 = fmaf(acc[fr][1][half * 2 + 1], -2.0f, c1.y);
                    float s4 = fmaf(acc[fr][2][half * 2 + 0], -2.0f, c2v.x);
                    float s5 = fmaf(acc[fr][2][half * 2 + 1], -2.0f, c2v.y);
                    float s6 = fmaf(acc[fr][3][half * 2 + 0], -2.0f, c3.x);
                    float s7 = fmaf(acc[fr][3][half * 2 + 1], -2.0f, c3.y);
                    float m = fminf(fminf(fminf(s0, s1), fminf(s2, s3)),
                                    fminf(fminf(s4, s5), fminf(s6, s7)));
                    BTOP6(m, gi, v[r][0], v[r][1], v[r][2], v[r][3], v[r][4],
                          v[r][5], g[r][0], g[r][1], g[r][2], g[r][3], g[r][4]);
                }
            }
        }

        __syncthreads();
        if (iter + 2 < 128) {
            const char* src = bsrc + (size_t)(iter + 2) * 64 * 256;
            uint32_t dstb = sb + ((iter & 1) ? SM_B1 : SM_B0);
            #pragma unroll
            for (int it = 0; it < 4; ++it) {
                int c   = it * 256 + tid;
                int row = c >> 4, col = c & 15;
                cp_async16(dstb + row * BSTRIDE + col * 16,
                           src + (size_t)row * 256 + col * 16);
            }
            CP_COMMIT();
            CP_WAIT1();
        } else {
            CP_WAIT0();
        }
        __syncthreads();
    }

    // write per-thread lists: row = mw*32 + fr*16 + half*8 + gq; list = nw*4+tq
    float* MV = (float*)(smraw + SM_MV);
    int*   MK = (int*)(smraw + SM_MK);
    {
        const int la = nw * 4 + tq;
        #pragma unroll
        for (int fr = 0; fr < 2; ++fr) {
            #pragma unroll
            for (int half = 0; half < 2; ++half) {
                const int r  = fr * 2 + half;
                const int ql = mw * 32 + fr * 16 + half * 8 + gq;
                const int vO = ql * 48 + la * 6;
                const int kO = ql * 40 + la * 5;
                #pragma unroll
                for (int j = 0; j < 6; ++j) MV[vO + j] = v[r][j];
                #pragma unroll
                for (int j = 0; j < 5; ++j) MK[kO + j] = g[r][j];
            }
        }
    }
    __syncthreads();

    // merge + computed rigorous window + group-candidate emission
    if (tid < 128) {
        const int q = n * BT + qbase + tid;
        float b1 = 3.4e38f;
        #pragma unroll
        for (int l = 0; l < 8; ++l)
            b1 = fminf(b1, MV[tid * 48 + l * 6]);
        float minv6 = 3.4e38f;
        #pragma unroll
        for (int l = 0; l < 8; ++l)
            minv6 = fminf(minv6, MV[tid * 48 + l * 6 + 5]);
        float cmax  = sqrtf(__int_as_float(g_c2max_bits[n]));
        float ecmax = sqrtf(__int_as_float(g_ec2max_bits[n]));
        float win = 4.0f * (sqrtf(g_ex2[q]) * cmax + sqrtf(g_xh2[q]) * ecmax)
                    + 2e-3f;
        float thr = b1 + win;

        int cnt;
        if (minv6 <= thr) {
            cnt = -1;
        } else {
            cnt = 0;
            #pragma unroll
            for (int l = 0; l < 8; ++l) {
                #pragma unroll
                for (int j = 0; j < 5; ++j) {
                    float vv = MV[tid * 48 + l * 6 + j];
                    if (vv <= thr) {
                        if (cnt < NCANDG)
                            g_candk[q * NCANDG + cnt] = MK[tid * 40 + l * 5 + j];
                        ++cnt;
                    }
                }
            }
            if (cnt > NCANDG) cnt = -1;
        }
        g_candn[q] = cnt;
    }
}

// ---------------------------------------------------------------------------
// exact JAX-order d2 (same arithmetic as all passing rounds)
// ---------------------------------------------------------------------------
__device__ __forceinline__ float exact_d2(const float* __restrict__ x,
                                          const float* __restrict__ cb,
                                          int n, int b, int t, int bt, int k) {
    const float* xp = x + ((size_t)b * CCH + (size_t)n * DDIM) * TLEN + t;
    const float* cp = cb + ((size_t)n * KCB + (size_t)k) * DDIM;
    float xc = 0.f;
    #pragma unroll 8
    for (int d = 0; d < DDIM; ++d) xc = fmaf(xp[(size_t)d * TLEN], cp[d], xc);
    return __fadd_rn(__fsub_rn(g_x2[n * BT + bt], __fmul_rn(2.0f, xc)),
                     g_c2[n * KCB + k]);
}

// ---------------------------------------------------------------------------
// finalize: 8 lanes per query; lane m rescores member m of each candidate
// group; 3-step shfl_xor segment-reduce. grid 512 x 256 (32 q/block).
// ---------------------------------------------------------------------------
__global__ void finalize_kernel(const float* __restrict__ x,
                                const float* __restrict__ cb,
                                float* __restrict__ out) {
    int q = blockIdx.x * 32 + (threadIdx.x >> 3);
    int m = threadIdx.x & 7;
    int n = q >> 13, bt = q & 8191, b = bt >> 10, t = bt & 1023;
    int cnt = g_candn[q];
    int work = (cnt < 0) ? 0 : cnt;

    float bd = 3.4e38f;
    int   kf = 1 << 30;
    for (int i = 0; i < work; ++i) {
        int base = g_candk[q * NCANDG + i];
        int k = base + (m >> 1) * 8 + (m & 1);
        float d = exact_d2(x, cb, n, b, t, bt, k);
        if (d < bd || (d == bd && k < kf)) { bd = d; kf = k; }
    }
    #pragma unroll
    for (int o = 4; o; o >>= 1) {
        float ov = __shfl_xor_sync(0xFFFFFFFFu, bd, o);
        int   ok = __shfl_xor_sync(0xFFFFFFFFu, kf, o);
        if (ov < bd || (ov == bd && ok < kf)) { bd = ov; kf = ok; }
    }
    if (m == 0) {
        if (cnt < 0) {
            int pos = atomicAdd(&g_nflag, 1);
            g_flagq[pos] = q;
        } else {
            g_idx[q] = kf;
            out[NQ + ((size_t)b * 2 + n) * TLEN + t] = (float)kf;
        }
    }
}

// ---------------------------------------------------------------------------
// fallback: PARALLEL exact full scan, one CTA per flagged query (strided)
// ---------------------------------------------------------------------------
__global__ void fallback_kernel(const float* __restrict__ x,
                                const float* __restrict__ cb,
                                float* __restrict__ out) {
    __shared__ float xq[128];
    __shared__ float sv[256];
    __shared__ int   sk[256];
    int nf = g_nflag;
    for (int i = blockIdx.x; i < nf; i += 256) {
        int q = g_flagq[i];
        int n = q >> 13, bt = q & 8191, b = bt >> 10, t = bt & 1023;
        if (threadIdx.x < 128)
            xq[threadIdx.x] = x[((size_t)b * CCH + (size_t)n * DDIM
                                 + threadIdx.x) * TLEN + t];
        __syncthreads();
        float x2v = g_x2[q];
        float bv = 3.4e38f;
        int   bk = 1 << 30;
        for (int j = 0; j < 32; ++j) {
            int k = j * 256 + threadIdx.x;
            const float* cp = cb + ((size_t)n * KCB + (size_t)k) * DDIM;
            float xc = 0.f;
            #pragma unroll 8
            for (int d = 0; d < DDIM; ++d) xc = fmaf(xq[d], cp[d], xc);
            float d2 = __fadd_rn(__fsub_rn(x2v, __fmul_rn(2.0f, xc)),
                                 g_c2[n * KCB + k]);
            if (d2 < bv || (d2 == bv && k < bk)) { bv = d2; bk = k; }
        }
        sv[threadIdx.x] = bv;
        sk[threadIdx.x] = bk;
        __syncthreads();
        for (int o = 128; o; o >>= 1) {
            if (threadIdx.x < o) {
                float ov = sv[threadIdx.x + o];
                int   ok = sk[threadIdx.x + o];
                if (ov < sv[threadIdx.x] ||
                    (ov == sv[threadIdx.x] && ok < sk[threadIdx.x])) {
                    sv[threadIdx.x] = ov; sk[threadIdx.x] = ok;
                }
            }
            __syncthreads();
        }
        if (threadIdx.x == 0) {
            g_idx[q] = sk[0];
            out[NQ + ((size_t)b * 2 + n) * TLEN + t] = (float)sk[0];
        }
        __syncthreads();
    }
}

// ---------------------------------------------------------------------------
// gather: coalesced quantized-output writes + commit-loss SSE
// ---------------------------------------------------------------------------
__global__ void gather_kernel(const float* __restrict__ x,
                              const float* __restrict__ cb,
                              float* __restrict__ out) {
    __shared__ float qs[128 * 33];
    __shared__ int   kq[32];
    __shared__ float red[8];
    int bi = blockIdx.x;
    int n  = bi >> 8;
    int b  = (bi >> 5) & 7;
    int tc = bi & 31;
    int tid = threadIdx.x;
    if (tid < 32) kq[tid] = g_idx[n * BT + b * TLEN + tc * 32 + tid];
    __syncthreads();
    #pragma unroll
    for (int j = 0; j < 16; ++j) {
        int idx = j * 256 + tid;
        int cw  = idx >> 7;
        int d   = idx & 127;
        qs[d * 33 + cw] = cb[((size_t)n * KCB + kq[cw]) * DDIM + d];
    }
    __syncthreads();
    float acc = 0.f;
    #pragma unroll
    for (int j = 0; j < 16; ++j) {
        int idx = j * 256 + tid;
        int d   = idx >> 5;
        int tt  = idx & 31;
        float w = qs[d * 33 + tt];
        size_t addr = ((size_t)b * CCH + (size_t)n * DDIM + d) * TLEN
                      + tc * 32 + tt;
        out[addr] = w;
        float df = x[addr] - w;
        acc += df * df;
    }
    #pragma unroll
    for (int o = 16; o; o >>= 1) acc += __shfl_down_sync(0xFFFFFFFFu, acc, o);
    if ((tid & 31) == 0) red[tid >> 5] = acc;
    __syncthreads();
    if (tid == 0) {
        float tot = 0.f;
        #pragma unroll
        for (int j = 0; j < 8; ++j) tot += red[j];
        atomicAdd(&g_sse, (double)tot);
    }
}

__global__ void fin_kernel(float* __restrict__ out) {
    out[NQ + NIDX] = (float)(0.25 * g_sse / (double)((long long)BT * DDIM));
}

// ---------------------------------------------------------------------------
extern "C" void kernel_launch(void* const* d_in, const int* in_sizes, int n_in,
                              void* d_out, int out_size) {
    const float* x  = (const float*)d_in[0];
    const float* cb = (const float*)d_in[1];
    float* out = (float*)d_out;

    cudaFuncSetAttribute(vq_mma_kernel,
                         cudaFuncAttributeMaxDynamicSharedMemorySize, SM_TOT);

    init_kernel<<<1, 32>>>();
    splitcb_kernel<<<2048, 256>>>(cb);
    split_x_kernel<<<512, 256>>>(x);
    vq_mma_kernel<<<128, 256, SM_TOT>>>();
    finalize_kernel<<<512, 256>>>(x, cb, out);
    fallback_kernel<<<256, 256>>>(x, cb, out);
    gather_kernel<<<512, 256>>>(x, cb, out);
    fin_kernel<<<1, 1>>>(out);
}